// round 1
// baseline (speedup 1.0000x reference)
#include <cuda_runtime.h>
#include <cuda_bf16.h>

// ChamferDistance: x,y [16, 4096, 3] fp32 -> scalar
// result = mean_b( mean_n min_m ||x_bn - y_bm||^2 + mean_m min_n ||...||^2 )

#define BATCH   16
#define NPTS    4096
#define TILE    2048
#define THREADS 128

__global__ void chamfer_zero_kernel(float* out) {
    out[0] = 0.0f;
}

__global__ __launch_bounds__(THREADS)
void chamfer_main_kernel(const float* __restrict__ x,
                         const float* __restrict__ y,
                         float* __restrict__ out) {
    // sh[i] = (-2*r0, -2*r1, -2*r2, r0^2+r1^2+r2^2)
    __shared__ float4 sh[TILE];
    __shared__ float warp_sums[THREADS / 32];

    const int dir = blockIdx.z;               // 0: x queries vs y refs, 1: swapped
    const float* q = (dir == 0) ? x : y;
    const float* r = (dir == 0) ? y : x;
    const int b = blockIdx.y;

    const int qi = blockIdx.x * THREADS + threadIdx.x;   // query index in [0,4096)
    const float* qp = q + ((size_t)b * NPTS + qi) * 3;
    const float qx = qp[0];
    const float qy = qp[1];
    const float qz = qp[2];

    const float* rbase = r + (size_t)b * NPTS * 3;

    float m0 = 3.402823466e38f;
    float m1 = 3.402823466e38f;
    float m2 = 3.402823466e38f;
    float m3 = 3.402823466e38f;

    for (int t = 0; t < NPTS; t += TILE) {
        // Cooperative load + transform of the reference tile.
        #pragma unroll
        for (int i = threadIdx.x; i < TILE; i += THREADS) {
            const float* rp = rbase + (size_t)(t + i) * 3;
            float r0 = rp[0];
            float r1 = rp[1];
            float r2 = rp[2];
            float n2 = fmaf(r0, r0, fmaf(r1, r1, r2 * r2));
            sh[i] = make_float4(-2.0f * r0, -2.0f * r1, -2.0f * r2, n2);
        }
        __syncthreads();

        #pragma unroll 4
        for (int i = 0; i < TILE; i += 4) {
            float4 a = sh[i + 0];
            float4 c = sh[i + 1];
            float4 d = sh[i + 2];
            float4 e = sh[i + 3];
            float t0 = fmaf(qx, a.x, fmaf(qy, a.y, fmaf(qz, a.z, a.w)));
            float t1 = fmaf(qx, c.x, fmaf(qy, c.y, fmaf(qz, c.z, c.w)));
            float t2 = fmaf(qx, d.x, fmaf(qy, d.y, fmaf(qz, d.z, d.w)));
            float t3 = fmaf(qx, e.x, fmaf(qy, e.y, fmaf(qz, e.z, e.w)));
            m0 = fminf(m0, t0);
            m1 = fminf(m1, t1);
            m2 = fminf(m2, t2);
            m3 = fminf(m3, t3);
        }
        __syncthreads();
    }

    // True min squared distance for this query point.
    float mn = fminf(fminf(m0, m1), fminf(m2, m3));
    float q2 = fmaf(qx, qx, fmaf(qy, qy, qz * qz));
    float val = q2 + mn;

    // Block reduction (sum of per-query NN distances).
    #pragma unroll
    for (int off = 16; off > 0; off >>= 1)
        val += __shfl_down_sync(0xFFFFFFFFu, val, off);

    const int lane = threadIdx.x & 31;
    const int wid = threadIdx.x >> 5;
    if (lane == 0) warp_sums[wid] = val;
    __syncthreads();

    if (wid == 0) {
        float s = (lane < THREADS / 32) ? warp_sums[lane] : 0.0f;
        #pragma unroll
        for (int off = 2; off > 0; off >>= 1)
            s += __shfl_down_sync(0xFFFFFFFFu, s, off);
        if (lane == 0) {
            // Final scalar = (sum over all queries, both dirs, all batches) / (B * N)
            const float scale = 1.0f / ((float)BATCH * (float)NPTS);
            atomicAdd(out, s * scale);
        }
    }
}

extern "C" void kernel_launch(void* const* d_in, const int* in_sizes, int n_in,
                              void* d_out, int out_size) {
    const float* x = (const float*)d_in[0];
    const float* y = (const float*)d_in[1];
    float* out = (float*)d_out;

    chamfer_zero_kernel<<<1, 1>>>(out);

    dim3 grid(NPTS / THREADS, BATCH, 2);   // 32 x 16 x 2 = 1024 blocks
    chamfer_main_kernel<<<grid, THREADS>>>(x, y, out);
}

// round 2
// speedup vs baseline: 1.5651x; 1.5651x over previous
#include <cuda_runtime.h>
#include <cuda_bf16.h>
#include <cstdint>

// ChamferDistance: x,y [16, 4096, 3] fp32 -> scalar
// Strategy: d(q, r) = ||q||^2 + dot4((qx,qy,qz,1), (-2rx,-2ry,-2rz,||r||^2))
// Packed f32x2 FMA processes 2 refs per op; Q=4 queries/thread amortizes LDS;
// refs split S=4 ways across blocks, partials merged with bitwise atomicMin.

#define BATCH   16
#define NPTS    4096
#define DIRS    2
#define THREADS 128
#define QPT     4                       // queries per thread
#define QBLK    (THREADS * QPT)         // 512 queries per block
#define SPLITS  4                       // ref-dimension splits
#define RTILE   (NPTS / SPLITS)         // 1024 refs per block
#define RPAIRS  (RTILE / 2)             // 512 packed ref pairs
#define QTILES  (NPTS / QBLK)           // 8 query tiles
#define TOTQ    (DIRS * BATCH * NPTS)   // 131072 scratch entries

__device__ float g_min[TOTQ];           // per-(dir,batch,query) NN sq-dist

// ---------- packed f32x2 helpers ----------
__device__ __forceinline__ unsigned long long ffma2(unsigned long long a,
                                                    unsigned long long b,
                                                    unsigned long long c) {
    unsigned long long d;
    asm("fma.rn.f32x2 %0, %1, %2, %3;" : "=l"(d) : "l"(a), "l"(b), "l"(c));
    return d;
}
__device__ __forceinline__ unsigned long long pack2(float lo, float hi) {
    unsigned long long d;
    asm("mov.b64 %0, {%1, %2};" : "=l"(d) : "r"(__float_as_uint(lo)), "r"(__float_as_uint(hi)));
    return d;
}
__device__ __forceinline__ void unpack2(unsigned long long v, float& lo, float& hi) {
    unsigned int l, h;
    asm("mov.b64 {%0, %1}, %2;" : "=r"(l), "=r"(h) : "l"(v));
    lo = __uint_as_float(l);
    hi = __uint_as_float(h);
}

// ---------- init: scratch = +inf, out = 0 ----------
__global__ void chamfer_init_kernel(float* out) {
    int i = blockIdx.x * blockDim.x + threadIdx.x;
    if (i < TOTQ) g_min[i] = __int_as_float(0x7f800000);
    if (i == 0) out[0] = 0.0f;
}

// ---------- main ----------
__global__ __launch_bounds__(THREADS)
void chamfer_main_kernel(const float* __restrict__ x,
                         const float* __restrict__ y) {
    __shared__ float4 shA[RPAIRS];   // (-2rx[2p], -2rx[2p+1], -2ry[2p], -2ry[2p+1])
    __shared__ float4 shB[RPAIRS];   // (-2rz[2p], -2rz[2p+1],  n2[2p],   n2[2p+1])

    const int qt  = blockIdx.x / SPLITS;      // query tile [0,8)
    const int s   = blockIdx.x % SPLITS;      // ref split  [0,4)
    const int b   = blockIdx.y;
    const int dir = blockIdx.z;

    const float* q = (dir == 0) ? x : y;
    const float* r = (dir == 0) ? y : x;
    const float* rbase = r + ((size_t)b * NPTS + s * RTILE) * 3;

    // Cooperative tile load + transform.
    for (int p = threadIdx.x; p < RPAIRS; p += THREADS) {
        const float* rp = rbase + (size_t)(2 * p) * 3;
        float a0 = rp[0], a1 = rp[1], a2 = rp[2];
        float b0 = rp[3], b1 = rp[4], b2 = rp[5];
        float na = fmaf(a0, a0, fmaf(a1, a1, a2 * a2));
        float nb = fmaf(b0, b0, fmaf(b1, b1, b2 * b2));
        shA[p] = make_float4(-2.0f * a0, -2.0f * b0, -2.0f * a1, -2.0f * b1);
        shB[p] = make_float4(-2.0f * a2, -2.0f * b2, na, nb);
    }

    // Per-thread query coordinates (Q=4), broadcast-packed.
    unsigned long long qx2[QPT], qy2[QPT], qz2[QPT];
    float q2[QPT];
    int qidx[QPT];
    #pragma unroll
    for (int k = 0; k < QPT; k++) {
        int qi = qt * QBLK + k * THREADS + threadIdx.x;
        qidx[k] = qi;
        const float* qp = q + ((size_t)b * NPTS + qi) * 3;
        float a = qp[0], c = qp[1], d = qp[2];
        qx2[k] = pack2(a, a);
        qy2[k] = pack2(c, c);
        qz2[k] = pack2(d, d);
        q2[k] = fmaf(a, a, fmaf(c, c, d * d));
    }

    __syncthreads();

    float mlo[QPT], mhi[QPT];
    #pragma unroll
    for (int k = 0; k < QPT; k++) {
        mlo[k] = __int_as_float(0x7f800000);
        mhi[k] = __int_as_float(0x7f800000);
    }

    const ulonglong2* __restrict__ A64 = reinterpret_cast<const ulonglong2*>(shA);
    const ulonglong2* __restrict__ B64 = reinterpret_cast<const ulonglong2*>(shB);

    #pragma unroll 4
    for (int j = 0; j < RPAIRS; j++) {
        ulonglong2 va = A64[j];   // .x = xp, .y = yp
        ulonglong2 vb = B64[j];   // .x = zp, .y = wp
        #pragma unroll
        for (int k = 0; k < QPT; k++) {
            unsigned long long t =
                ffma2(qx2[k], va.x, ffma2(qy2[k], va.y, ffma2(qz2[k], vb.x, vb.y)));
            float tl, th;
            unpack2(t, tl, th);
            mlo[k] = fminf(mlo[k], tl);
            mhi[k] = fminf(mhi[k], th);
        }
    }

    // Merge partial mins into global scratch (bit-compare valid: vals >= 0).
    #pragma unroll
    for (int k = 0; k < QPT; k++) {
        float val = fmaxf(q2[k] + fminf(mlo[k], mhi[k]), 0.0f);
        int* addr = (int*)&g_min[(size_t)dir * BATCH * NPTS + (size_t)b * NPTS + qidx[k]];
        atomicMin(addr, __float_as_int(val));
    }
}

// ---------- final reduction ----------
#define RBLOCKS 64
#define RTHREADS 256
__global__ void chamfer_reduce_kernel(float* __restrict__ out) {
    __shared__ float wsum[RTHREADS / 32];
    float s = 0.0f;
    for (int i = blockIdx.x * RTHREADS + threadIdx.x; i < TOTQ; i += RBLOCKS * RTHREADS)
        s += g_min[i];
    #pragma unroll
    for (int off = 16; off > 0; off >>= 1)
        s += __shfl_down_sync(0xFFFFFFFFu, s, off);
    int lane = threadIdx.x & 31, wid = threadIdx.x >> 5;
    if (lane == 0) wsum[wid] = s;
    __syncthreads();
    if (wid == 0) {
        float v = (lane < RTHREADS / 32) ? wsum[lane] : 0.0f;
        #pragma unroll
        for (int off = 4; off > 0; off >>= 1)
            v += __shfl_down_sync(0xFFFFFFFFu, v, off);
        if (lane == 0)
            atomicAdd(out, v * (1.0f / ((float)BATCH * (float)NPTS)));
    }
}

extern "C" void kernel_launch(void* const* d_in, const int* in_sizes, int n_in,
                              void* d_out, int out_size) {
    const float* x = (const float*)d_in[0];
    const float* y = (const float*)d_in[1];
    float* out = (float*)d_out;

    chamfer_init_kernel<<<(TOTQ + 255) / 256, 256>>>(out);

    dim3 grid(QTILES * SPLITS, BATCH, DIRS);   // 32 x 16 x 2 = 1024 blocks
    chamfer_main_kernel<<<grid, THREADS>>>(x, y);

    chamfer_reduce_kernel<<<RBLOCKS, RTHREADS>>>(out);
}

// round 3
// speedup vs baseline: 1.6918x; 1.0809x over previous
#include <cuda_runtime.h>
#include <cuda_bf16.h>
#include <cstdint>

// ChamferDistance: x,y [16, 4096, 3] fp32 -> scalar
// d(q,r) = ||q||^2 + dot4((qx,qy,qz,1), (-2rx,-2ry,-2rz,||r||^2))
// Packed f32x2 FMA (2 refs/op). QPT=2 queries/thread. SPLITS=4 ref splits,
// partial NN mins plain-stored to scratch, combined in a 2-stage reduce
// (no init kernel, no atomics anywhere).

#define BATCH   16
#define NPTS    4096
#define DIRS    2
#define THREADS 128
#define QPT     2                         // queries per thread
#define QBLK    (THREADS * QPT)           // 256 queries per block
#define SPLITS  4                         // ref-dimension splits
#define RTILE   (NPTS / SPLITS)           // 1024 refs per block
#define RPAIRS  (RTILE / 2)               // 512 packed ref pairs
#define QTILES  (NPTS / QBLK)             // 16 query tiles
#define TOTQ    (DIRS * BATCH * NPTS)     // 131072 queries total

#define R1BLOCKS  256
#define R1THREADS 256
#define R2THREADS 256

__device__ float g_part[SPLITS][TOTQ];    // partial NN sq-dists (2 MB)
__device__ float g_bsum[R1BLOCKS];        // stage-1 block sums

// ---------- packed f32x2 helpers ----------
__device__ __forceinline__ unsigned long long ffma2(unsigned long long a,
                                                    unsigned long long b,
                                                    unsigned long long c) {
    unsigned long long d;
    asm("fma.rn.f32x2 %0, %1, %2, %3;" : "=l"(d) : "l"(a), "l"(b), "l"(c));
    return d;
}
__device__ __forceinline__ unsigned long long pack2(float lo, float hi) {
    unsigned long long d;
    asm("mov.b64 %0, {%1, %2};" : "=l"(d) : "r"(__float_as_uint(lo)), "r"(__float_as_uint(hi)));
    return d;
}
__device__ __forceinline__ void unpack2(unsigned long long v, float& lo, float& hi) {
    unsigned int l, h;
    asm("mov.b64 {%0, %1}, %2;" : "=r"(l), "=r"(h) : "l"(v));
    lo = __uint_as_float(l);
    hi = __uint_as_float(h);
}

// ---------- main ----------
__global__ __launch_bounds__(THREADS)
void chamfer_main_kernel(const float* __restrict__ x,
                         const float* __restrict__ y) {
    __shared__ float4 shA[RPAIRS];   // (-2rx[2p], -2rx[2p+1], -2ry[2p], -2ry[2p+1])
    __shared__ float4 shB[RPAIRS];   // (-2rz[2p], -2rz[2p+1],  n2[2p],   n2[2p+1])

    const int qt  = blockIdx.x >> 2;          // query tile [0,16)
    const int s   = blockIdx.x & 3;           // ref split  [0,4)
    const int b   = blockIdx.y;
    const int dir = blockIdx.z;

    const float* q = (dir == 0) ? x : y;
    const float* r = (dir == 0) ? y : x;
    const float* rbase = r + ((size_t)b * NPTS + s * RTILE) * 3;

    // Cooperative tile load + transform (4 pairs per thread).
    #pragma unroll
    for (int p = threadIdx.x; p < RPAIRS; p += THREADS) {
        const float* rp = rbase + (size_t)(2 * p) * 3;
        float a0 = rp[0], a1 = rp[1], a2 = rp[2];
        float b0 = rp[3], b1 = rp[4], b2 = rp[5];
        float na = fmaf(a0, a0, fmaf(a1, a1, a2 * a2));
        float nb = fmaf(b0, b0, fmaf(b1, b1, b2 * b2));
        shA[p] = make_float4(-2.0f * a0, -2.0f * b0, -2.0f * a1, -2.0f * b1);
        shB[p] = make_float4(-2.0f * a2, -2.0f * b2, na, nb);
    }

    // Per-thread query coordinates (QPT=2), broadcast-packed.
    unsigned long long qx2[QPT], qy2[QPT], qz2[QPT];
    float q2[QPT];
    int qidx[QPT];
    #pragma unroll
    for (int k = 0; k < QPT; k++) {
        int qi = qt * QBLK + k * THREADS + threadIdx.x;
        qidx[k] = qi;
        const float* qp = q + ((size_t)b * NPTS + qi) * 3;
        float a = qp[0], c = qp[1], d = qp[2];
        qx2[k] = pack2(a, a);
        qy2[k] = pack2(c, c);
        qz2[k] = pack2(d, d);
        q2[k] = fmaf(a, a, fmaf(c, c, d * d));
    }

    __syncthreads();

    float mlo[QPT], mhi[QPT];
    #pragma unroll
    for (int k = 0; k < QPT; k++) {
        mlo[k] = __int_as_float(0x7f800000);
        mhi[k] = __int_as_float(0x7f800000);
    }

    const ulonglong2* __restrict__ A64 = reinterpret_cast<const ulonglong2*>(shA);
    const ulonglong2* __restrict__ B64 = reinterpret_cast<const ulonglong2*>(shB);

    #pragma unroll 8
    for (int j = 0; j < RPAIRS; j++) {
        ulonglong2 va = A64[j];   // .x = xpair, .y = ypair
        ulonglong2 vb = B64[j];   // .x = zpair, .y = n2pair
        #pragma unroll
        for (int k = 0; k < QPT; k++) {
            unsigned long long t =
                ffma2(qx2[k], va.x, ffma2(qy2[k], va.y, ffma2(qz2[k], vb.x, vb.y)));
            float tl, th;
            unpack2(t, tl, th);
            mlo[k] = fminf(mlo[k], tl);
            mhi[k] = fminf(mhi[k], th);
        }
    }

    // Plain store of per-split partial NN distance (no atomics, no init needed).
    #pragma unroll
    for (int k = 0; k < QPT; k++) {
        float val = q2[k] + fminf(mlo[k], mhi[k]);
        g_part[s][(size_t)dir * BATCH * NPTS + (size_t)b * NPTS + qidx[k]] = val;
    }
}

// ---------- stage 1: min over splits + block sums ----------
__global__ __launch_bounds__(R1THREADS)
void chamfer_reduce1_kernel() {
    __shared__ float wsum[R1THREADS / 32];
    float s = 0.0f;
    for (int i = blockIdx.x * R1THREADS + threadIdx.x; i < TOTQ; i += R1BLOCKS * R1THREADS) {
        float m = g_part[0][i];
        m = fminf(m, g_part[1][i]);
        m = fminf(m, g_part[2][i]);
        m = fminf(m, g_part[3][i]);
        s += m;
    }
    #pragma unroll
    for (int off = 16; off > 0; off >>= 1)
        s += __shfl_down_sync(0xFFFFFFFFu, s, off);
    int lane = threadIdx.x & 31, wid = threadIdx.x >> 5;
    if (lane == 0) wsum[wid] = s;
    __syncthreads();
    if (wid == 0) {
        float v = (lane < R1THREADS / 32) ? wsum[lane] : 0.0f;
        #pragma unroll
        for (int off = 4; off > 0; off >>= 1)
            v += __shfl_down_sync(0xFFFFFFFFu, v, off);
        if (lane == 0) g_bsum[blockIdx.x] = v;
    }
}

// ---------- stage 2: final sum, overwrite out ----------
__global__ __launch_bounds__(R2THREADS)
void chamfer_reduce2_kernel(float* __restrict__ out) {
    __shared__ float wsum[R2THREADS / 32];
    float s = (threadIdx.x < R1BLOCKS) ? g_bsum[threadIdx.x] : 0.0f;
    #pragma unroll
    for (int off = 16; off > 0; off >>= 1)
        s += __shfl_down_sync(0xFFFFFFFFu, s, off);
    int lane = threadIdx.x & 31, wid = threadIdx.x >> 5;
    if (lane == 0) wsum[wid] = s;
    __syncthreads();
    if (wid == 0) {
        float v = (lane < R2THREADS / 32) ? wsum[lane] : 0.0f;
        #pragma unroll
        for (int off = 4; off > 0; off >>= 1)
            v += __shfl_down_sync(0xFFFFFFFFu, v, off);
        if (lane == 0)
            out[0] = v * (1.0f / ((float)BATCH * (float)NPTS));
    }
}

extern "C" void kernel_launch(void* const* d_in, const int* in_sizes, int n_in,
                              void* d_out, int out_size) {
    const float* x = (const float*)d_in[0];
    const float* y = (const float*)d_in[1];
    float* out = (float*)d_out;

    dim3 grid(QTILES * SPLITS, BATCH, DIRS);   // 64 x 16 x 2 = 2048 blocks
    chamfer_main_kernel<<<grid, THREADS>>>(x, y);

    chamfer_reduce1_kernel<<<R1BLOCKS, R1THREADS>>>();
    chamfer_reduce2_kernel<<<1, R2THREADS>>>(out);
}